// round 12
// baseline (speedup 1.0000x reference)
#include <cuda_runtime.h>
#include <cuda_bf16.h>
#include <cuda_fp16.h>
#include <math.h>
#include <stdint.h>

#define NTn     34000
#define NTYPES  3
#define NMP     2
#define ECNT    300000
#define HH      8
#define DD      64
#define HDIM    512
#define AVd     128
#define COUT    8
#define NTGTn   1000
#define NNODES  (NTYPES*NTn)
#define NSLAB   (NTYPES*NMP)

// ---------------- scratch (device globals; no allocation) ----------------
__device__ float g_h0[(size_t)NNODES*DD];
__device__ float g_h1[(size_t)NNODES*DD];
__device__ __half g_hh[(size_t)NNODES*DD];   // fp16 mirror of current-layer h (gathers)
// st as split bf16 (big + residual); +128 rows padding so tile tails stay in-bounds
__device__ __nv_bfloat16 g_stb[((size_t)NSLAB*NTn + 128)*HDIM];
__device__ __nv_bfloat16 g_sts[((size_t)NSLAB*NTn + 128)*HDIM];
__device__ float g_u [(size_t)NSLAB*NTn*HH];
__device__ float g_t2[(size_t)NSLAB*NNODES*HH];
__device__ int2  g_srt[(size_t)NSLAB*ECNT];      // sorted (n1,n2); n0 = ibase + segment
__device__ int   g_counts[NSLAB*NTn];            // zero-init at load; scan re-zeroes
__device__ int   g_ofs   [NSLAB*NTn];
__device__ int   g_cursor[NSLAB*NTn];
__device__ float g_s[NSLAB];
__device__ __nv_bfloat16 g_bt[(size_t)(NTYPES+1)*AVd*HDIM];  // mpW^T bf16
// split-bf16 transposed weights [64][K]: fc0(K512), fc1(K256), fc2(K128), lW0(K512)
#define WOFF0 0
#define WOFF1 (64*512)
#define WOFF2 (WOFF1 + 64*256)
#define WOFF3 (WOFF2 + 64*128)
#define WTOT  (WOFF3 + 64*512)
__device__ __nv_bfloat16 g_wb[WTOT];
__device__ __nv_bfloat16 g_ws[WTOT];

__device__ __forceinline__ float tanh_apx(float x) {
    float y; asm("tanh.approx.f32 %0, %1;" : "=f"(y) : "f"(x)); return y;
}
__device__ __forceinline__ uint32_t smem_u32(const void* p) {
    uint32_t a;
    asm("{ .reg .u64 t; cvta.to.shared.u64 t, %1; cvt.u32.u64 %0, t; }"
        : "=r"(a) : "l"(p));
    return a;
}
__device__ __forceinline__ float bf2f(__nv_bfloat16 x) { return __bfloat162float(x); }
__device__ __forceinline__ uint32_t pk2(__nv_bfloat16 a, __nv_bfloat16 b) {
    __nv_bfloat162 p = __halves2bfloat162(a, b);
    return *(uint32_t*)&p;
}
__device__ __forceinline__ uint32_t pk2h(__half a, __half b) {
    __half2 p = __halves2half2(a, b);
    return *(uint32_t*)&p;
}

// ---------------- weight prep: fc/lW0 split-transpose + mpW transpose ----------
struct PArgs { const float* W; int K; int off; };
struct PArgs4 { PArgs z[4]; };
__global__ void prepW_kernel(PArgs4 pa, const float* __restrict__ mpW) {
    int zz = blockIdx.z;
    int idx = blockIdx.x*256 + threadIdx.x;
    if (zz < 4) {
        PArgs g = pa.z[zz];
        if (idx < 64*g.K) {
            int n = idx & 63;
            int k = idx >> 6;
            float v = g.W[(size_t)k*64 + n];
            __nv_bfloat16 big = __float2bfloat16_rn(v);
            g_wb[g.off + (size_t)n*g.K + k] = big;
            g_ws[g.off + (size_t)n*g.K + k] = __float2bfloat16_rn(v - bf2f(big));
        }
    } else {
        int mi = zz - 4;
        if (idx < AVd*HDIM) {
            int n = idx >> 9;
            int k = idx & 511;
            float v = mpW[(size_t)mi*HDIM*AVd + (size_t)k*AVd + n];
            g_bt[(size_t)mi*AVd*HDIM + (size_t)n*HDIM + k] = __float2bfloat16(v);
        }
    }
}

// ---------------- CSR construction ----------------
__global__ void hist_kernel(const int* __restrict__ mpidx, int* __restrict__ counts) {
    int slab = blockIdx.z;
    int e = blockIdx.x*blockDim.x + threadIdx.x;
    if (e < ECNT) {
        int dst = mpidx[(size_t)slab*ECNT*3 + e*3] - (slab/NMP)*NTn;
        atomicAdd(&counts[(size_t)slab*NTn + dst], 1);
    }
}

__global__ void scan_kernel(int* __restrict__ countsAll,
                            int* __restrict__ ofsAll, int* __restrict__ cursorAll) {
    int slab = blockIdx.x;
    int4* counts4 = (int4*)(countsAll + (size_t)slab*NTn);
    int4* ofs4    = (int4*)(ofsAll    + (size_t)slab*NTn);
    int4* cursor4 = (int4*)(cursorAll + (size_t)slab*NTn);
    const int N4 = NTn/4;
    __shared__ int warp_sums[32];
    __shared__ int s_carry;
    if (threadIdx.x == 0) s_carry = 0;
    __syncthreads();
    int lane = threadIdx.x & 31, wid = threadIdx.x >> 5;
    for (int base = 0; base < N4; base += 1024) {
        int i4 = base + threadIdx.x;
        int4 v = (i4 < N4) ? counts4[i4] : make_int4(0,0,0,0);
        if (i4 < N4) counts4[i4] = make_int4(0,0,0,0);   // re-zero for next run
        int c1 = v.x, c2 = c1 + v.y, c3 = c2 + v.z, c4 = c3 + v.w;
        int tot = c4;
        int incl = tot;
        #pragma unroll
        for (int d = 1; d < 32; d <<= 1) {
            int t = __shfl_up_sync(0xffffffffu, incl, d);
            if (lane >= d) incl += t;
        }
        if (lane == 31) warp_sums[wid] = incl;
        __syncthreads();
        if (wid == 0) {
            int w = warp_sums[lane];
            #pragma unroll
            for (int d = 1; d < 32; d <<= 1) {
                int t = __shfl_up_sync(0xffffffffu, w, d);
                if (lane >= d) w += t;
            }
            warp_sums[lane] = w;
        }
        __syncthreads();
        int add = s_carry + (wid > 0 ? warp_sums[wid-1] : 0);
        int be  = add + incl - tot;
        if (i4 < N4) {
            int4 o = make_int4(be, be + c1, be + c2, be + c3);
            ofs4[i4] = o;
            cursor4[i4] = o;
        }
        __syncthreads();
        if (threadIdx.x == 1023) s_carry = add + incl;
        __syncthreads();
    }
}

__global__ void scatter_kernel(const int* __restrict__ mpidx, int* __restrict__ cursorAll) {
    int slab = blockIdx.z;
    int e = blockIdx.x*blockDim.x + threadIdx.x;
    if (e < ECNT) {
        const int* mp = mpidx + (size_t)slab*ECNT*3 + (size_t)e*3;
        int n0 = mp[0], n1 = mp[1], n2 = mp[2];
        int dst = n0 - (slab/NMP)*NTn;
        int pos = atomicAdd(&cursorAll[(size_t)slab*NTn + dst], 1);
        g_srt[(size_t)slab*ECNT + pos] = make_int2(n1, n2);
    }
}

// ---------------- per-node attention dots (warp/node, both metapaths of a type) ----
__global__ __launch_bounds__(256)
void dot_kernel(const float* __restrict__ h, const float* __restrict__ attn1,
                const float* __restrict__ attn2, int layerOff) {
    int type = blockIdx.z;
    size_t base = (size_t)(layerOff + type*NMP)*HH*DD;
    __shared__ float a1s[NMP*HH*DD];
    __shared__ float a2s[NMP*HH*DD];
    for (int i = threadIdx.x; i < NMP*HH*DD; i += blockDim.x) {
        a1s[i] = attn1[base + i];
        a2s[i] = attn2[base + i];
    }
    if (blockIdx.x == 0 && blockIdx.z == 0 && threadIdx.x < NSLAB)
        g_s[threadIdx.x] = 0.f;
    __syncthreads();
    int lane = threadIdx.x & 31;
    int wid  = threadIdx.x >> 5;
    int gn = blockIdx.x*8 + wid;
    if (gn >= NNODES) return;

    float hv0 = h[(size_t)gn*DD + lane];
    float hv1 = h[(size_t)gn*DD + 32 + lane];
    int ibase = type*NTn;
    bool isdst = (gn >= ibase) && (gn < ibase + NTn);
    const float third = 1.f/3.f;

    #pragma unroll
    for (int p = 0; p < NMP; p++) {
        int slab = type*NMP + p;
        const float* a2p = a2s + p*HH*DD;
        const float* a1p = a1s + p*HH*DD;
        float r2[HH], r1[HH];
        #pragma unroll
        for (int hh = 0; hh < HH; hh++) {
            float v = hv0*a2p[hh*DD+lane] + hv1*a2p[hh*DD+32+lane];
            #pragma unroll
            for (int o = 16; o > 0; o >>= 1) v += __shfl_xor_sync(0xffffffffu, v, o);
            r2[hh] = v;
        }
        if (isdst) {
            #pragma unroll
            for (int hh = 0; hh < HH; hh++) {
                float v = hv0*a1p[hh*DD+lane] + hv1*a1p[hh*DD+32+lane];
                #pragma unroll
                for (int o = 16; o > 0; o >>= 1) v += __shfl_xor_sync(0xffffffffu, v, o);
                r1[hh] = v;
            }
        }
        float myt2 = 0.f, myu = 0.f;
        #pragma unroll
        for (int hh = 0; hh < HH; hh++) {
            if (lane == hh) {
                myt2 = r2[hh];
                if (isdst) myu = r1[hh] + r2[hh]*third;
            }
        }
        if (lane < HH) {
            g_t2[((size_t)slab*NNODES + gn)*HH + lane] = myt2;
            if (isdst) g_u[((size_t)slab*NTn + (gn - ibase))*HH + lane] = myu;
        }
    }
}

// ---------------- fused logits + segment softmax + weighted sum (warp/node) -----
// fp16 mid-node gathers (lane owns dims 2*lane, 2*lane+1); n0 term fp32; split-bf16 st.
__global__ __launch_bounds__(256)
void node_kernel(const __half* __restrict__ hh16, const float* __restrict__ hf) {
    int slab = blockIdx.z;
    const int*  ofs = g_ofs + (size_t)slab*NTn;
    const int2* srt = g_srt + (size_t)slab*ECNT;
    const float* t2b = g_t2 + (size_t)slab*NNODES*HH;
    const float* ub  = g_u  + (size_t)slab*NTn*HH;
    __nv_bfloat16* stb = g_stb + (size_t)slab*NTn*HDIM;
    __nv_bfloat16* sts = g_sts + (size_t)slab*NTn*HDIM;

    int lane = threadIdx.x & 31;
    int wid  = threadIdx.x >> 5;
    int n = blockIdx.x*8 + wid;
    if (n >= NTn) return;

    int s0 = ofs[n];
    int s1 = (n < NTn-1) ? ofs[n+1] : ECNT;
    int d0 = 2*lane;   // dims handled by this lane
    if (s1 == s0) {   // empty segment -> st row = elu(0) = 0
        uint32_t z = 0;
        #pragma unroll
        for (int hd = 0; hd < HH; hd++) {
            *(uint32_t*)&stb[(size_t)n*HDIM + hd*DD + d0] = z;
            *(uint32_t*)&sts[(size_t)n*HDIM + hd*DD + d0] = z;
        }
        return;
    }
    int ibase = (slab/NMP)*NTn;

    const int h_my = lane & 7;    // head handled by this lane for ex
    const int c_my = lane >> 3;   // chunk-slot handled by this lane for ex
    float u_my = ub[(size_t)n*HH + h_my];
    float2 hn0p = *(const float2*)&hf[(size_t)(ibase+n)*DD + d0];  // n0 term fp32
    float hn0a = hn0p.x;
    float hn0b = hn0p.y;
    const float third = 1.f/3.f;

    float den_l = 0.f;
    float acc[2*HH];
    #pragma unroll
    for (int k = 0; k < 2*HH; k++) acc[k] = 0.f;

    // prime the index pipeline
    int2 cur[4];
    #pragma unroll
    for (int c = 0; c < 4; c++) {
        int jj = s0 + c; if (jj >= s1) jj = s1 - 1;
        cur[c] = srt[jj];
    }

    for (int j = s0; j < s1; j += 4) {
        int2 nxt[4];
        int jn = j + 4;
        #pragma unroll
        for (int c = 0; c < 4; c++) {
            int jj = jn + c; if (jj >= s1) jj = s1 - 1;
            nxt[c] = srt[jj];
        }
        int m = s1 - j; if (m > 4) m = 4;
        int nn1[4], nn2[4];
        #pragma unroll
        for (int c = 0; c < 4; c++) { nn1[c] = cur[c].x; nn2[c] = cur[c].y; }
        float ta = t2b[(size_t)nn1[c_my]*HH + h_my];
        float tb = t2b[(size_t)nn2[c_my]*HH + h_my];
        // fp16 feature gathers: one 128B wavefront per row
        __half2 p1[4], p2[4];
        #pragma unroll
        for (int c = 0; c < 4; c++) {
            p1[c] = *(const __half2*)&hh16[(size_t)nn1[c]*DD + d0];
            p2[c] = *(const __half2*)&hh16[(size_t)nn2[c]*DD + d0];
        }
        float ev = u_my + (ta + tb)*third;
        ev = (ev > 0.f) ? ev : 0.2f*ev;          // leaky_relu 0.2
        float ex = (c_my < m) ? __expf(ev) : 0.f;
        den_l += ex;
        #pragma unroll
        for (int c = 0; c < 4; c++) {
            float2 f1 = __half22float2(p1[c]);
            float2 f2 = __half22float2(p2[c]);
            float sa = f1.x + f2.x;
            float sb = f1.y + f2.y;
            #pragma unroll
            for (int hd = 0; hd < HH; hd++) {
                float exh = __shfl_sync(0xffffffffu, ex, c*8 + hd);
                acc[hd*2+0] += exh * sa;
                acc[hd*2+1] += exh * sb;
            }
        }
        #pragma unroll
        for (int c = 0; c < 4; c++) cur[c] = nxt[c];
    }

    // den: sum over chunk-slot groups (bits 3,4); head preserved in low 3 bits
    den_l += __shfl_xor_sync(0xffffffffu, den_l, 8);
    den_l += __shfl_xor_sync(0xffffffffu, den_l, 16);

    #pragma unroll
    for (int hd = 0; hd < HH; hd++) {
        float dh = __shfl_sync(0xffffffffu, den_l, hd);
        float inv = 1.f / dh;
        float v0 = (hn0a + acc[hd*2+0]*inv) * third;
        float v1 = (hn0b + acc[hd*2+1]*inv) * third;
        v0 = (v0 > 0.f) ? v0 : (__expf(v0) - 1.f);
        v1 = (v1 > 0.f) ? v1 : (__expf(v1) - 1.f);
        __nv_bfloat16 b0 = __float2bfloat16_rn(v0);
        __nv_bfloat16 b1 = __float2bfloat16_rn(v1);
        *(uint32_t*)&stb[(size_t)n*HDIM + hd*DD + d0] = pk2(b0, b1);
        *(uint32_t*)&sts[(size_t)n*HDIM + hd*DD + d0] =
            pk2(__float2bfloat16_rn(v0 - bf2f(b0)), __float2bfloat16_rn(v1 - bf2f(b1)));
    }
}

// ---------------- HMMA bf16 mode-1 GEMM: s += sum_rows(tanh(A@B^T + bias).q) ----
struct T1Args { const __nv_bfloat16* A; const __nv_bfloat16* Bt;
                const float* bias; const float* q; float* sOut; };
struct T1ArgsN { T1Args z[NSLAB]; };

__global__ __launch_bounds__(256)
void mp_attn_kernel(int M, T1ArgsN ga) {
    constexpr int AP = 72;
    __shared__ __align__(16) __nv_bfloat16 As[128*AP];
    __shared__ __align__(16) __nv_bfloat16 Bs[128*AP];
    __shared__ float sb_bias[128], sb_q[128];
    __shared__ float red[256];
    const T1Args g = ga.z[blockIdx.z];
    const int tid  = threadIdx.x;
    const int wid  = tid >> 5;
    const int lane = tid & 31;
    const int mBase = blockIdx.x * 128;
    const int wm = (wid >> 2) * 64;
    const int wn = (wid & 3) * 32;

    if (tid < 128) { sb_bias[tid] = g.bias[tid]; sb_q[tid] = g.q[tid]; }

    float d[4][4][4];
    #pragma unroll
    for (int mt = 0; mt < 4; mt++)
        #pragma unroll
        for (int nt = 0; nt < 4; nt++)
            #pragma unroll
            for (int f = 0; f < 4; f++) d[mt][nt][f] = 0.f;

    uint4 ra[4], rb[4];
    int rowm[4], colm[4];
    #pragma unroll
    for (int i = 0; i < 4; i++) {
        int t = tid + i*256;
        rowm[i] = t >> 3;
        colm[i] = (t & 7) * 8;
    }

    auto loadRegs = [&](int c) {
        #pragma unroll
        for (int i = 0; i < 4; i++) {
            ra[i] = *(const uint4*)(g.A  + (size_t)(mBase + rowm[i])*HDIM + c*64 + colm[i]);
            rb[i] = *(const uint4*)(g.Bt + (size_t)rowm[i]*HDIM + c*64 + colm[i]);
        }
    };
    auto storeSmem = [&]() {
        #pragma unroll
        for (int i = 0; i < 4; i++) {
            *(uint4*)&As[rowm[i]*AP + colm[i]] = ra[i];
            *(uint4*)&Bs[rowm[i]*AP + colm[i]] = rb[i];
        }
    };

    uint32_t aSb = smem_u32(As);
    uint32_t bSb = smem_u32(Bs);

    loadRegs(0);
    #pragma unroll 1
    for (int c = 0; c < 8; c++) {
        storeSmem();
        __syncthreads();
        if (c < 7) loadRegs(c + 1);
        #pragma unroll
        for (int ks = 0; ks < 4; ks++) {
            uint32_t af[4][4];
            #pragma unroll
            for (int mt = 0; mt < 4; mt++) {
                uint32_t addr = aSb +
                    (((wm + mt*16 + (lane & 15))*AP + ks*16 + (lane >> 4)*8) << 1);
                asm volatile("ldmatrix.sync.aligned.m8n8.x4.shared.b16 {%0,%1,%2,%3}, [%4];"
                    : "=r"(af[mt][0]), "=r"(af[mt][1]), "=r"(af[mt][2]), "=r"(af[mt][3])
                    : "r"(addr));
            }
            uint32_t bf[4][2];
            #pragma unroll
            for (int nt = 0; nt < 4; nt++) {
                uint32_t addr = bSb +
                    (((wn + nt*8 + (lane & 7))*AP + ks*16 + ((lane >> 3) & 1)*8) << 1);
                asm volatile("ldmatrix.sync.aligned.m8n8.x2.shared.b16 {%0,%1}, [%2];"
                    : "=r"(bf[nt][0]), "=r"(bf[nt][1])
                    : "r"(addr));
            }
            #pragma unroll
            for (int mt = 0; mt < 4; mt++)
                #pragma unroll
                for (int nt = 0; nt < 4; nt++)
                    asm volatile(
                        "mma.sync.aligned.m16n8k16.row.col.f32.bf16.bf16.f32 "
                        "{%0,%1,%2,%3}, {%4,%5,%6,%7}, {%8,%9}, {%0,%1,%2,%3};"
                        : "+f"(d[mt][nt][0]), "+f"(d[mt][nt][1]),
                          "+f"(d[mt][nt][2]), "+f"(d[mt][nt][3])
                        : "r"(af[mt][0]), "r"(af[mt][1]), "r"(af[mt][2]), "r"(af[mt][3]),
                          "r"(bf[nt][0]), "r"(bf[nt][1]));
        }
        __syncthreads();
    }

    int g8  = lane >> 2;
    int tig = lane & 3;
    float local = 0.f;
    #pragma unroll
    for (int mt = 0; mt < 4; mt++) {
        int r0 = mBase + wm + mt*16 + g8;
        int r1 = r0 + 8;
        #pragma unroll
        for (int nt = 0; nt < 4; nt++) {
            int c0 = wn + nt*8 + 2*tig;
            float b0v = sb_bias[c0],   q0v = sb_q[c0];
            float b1v = sb_bias[c0+1], q1v = sb_q[c0+1];
            if (r0 < M)
                local += tanh_apx(d[mt][nt][0] + b0v)*q0v
                       + tanh_apx(d[mt][nt][1] + b1v)*q1v;
            if (r1 < M)
                local += tanh_apx(d[mt][nt][2] + b0v)*q0v
                       + tanh_apx(d[mt][nt][3] + b1v)*q1v;
        }
    }
    red[tid] = local;
    __syncthreads();
    if (tid < 128) red[tid] += red[tid + 128];
    __syncthreads();
    if (tid < 64) red[tid] += red[tid + 64];
    __syncthreads();
    if (tid < 32) {
        float v = red[tid] + red[tid + 32];
        #pragma unroll
        for (int o = 16; o > 0; o >>= 1) v += __shfl_xor_sync(0xffffffffu, v, o);
        if (tid == 0) atomicAdd(g.sOut, v);
    }
}

// ---------------- split-bf16 HMMA GEMM: N=64 ----------------
// MODE 0: C = A0(fp32) @ W + bias    (W pre-split bf16; A split inline)
// MODE 2: C = elu( (b0*(A0b+A0s) + b1*(A1b+A1s)) @ W + bias ), A pre-split bf16
// Both modes also write fp16 mirror Ch.
struct HArgs { const float* A0;
               const __nv_bfloat16* A0b; const __nv_bfloat16* A0s;
               const __nv_bfloat16* A1b; const __nv_bfloat16* A1s;
               const __nv_bfloat16* Bb;  const __nv_bfloat16* Bs2;
               const float* bias; float* C; __half* Ch; int K; int sIdx; };
struct HArgsN { HArgs z[NTYPES]; };

template<int MODE>
__global__ __launch_bounds__(256)
void hgemm_kernel(int M, HArgsN ga) {
    constexpr int AP = 72;
    __shared__ __align__(16) __nv_bfloat16 AsB[128*AP];
    __shared__ __align__(16) __nv_bfloat16 AsS[128*AP];
    __shared__ __align__(16) __nv_bfloat16 BsB[64*AP];
    __shared__ __align__(16) __nv_bfloat16 BsS[64*AP];
    __shared__ float sb_bias[64];
    __shared__ float sb_beta[2];
    const HArgs g = ga.z[blockIdx.z];
    const int tid  = threadIdx.x;
    const int wid  = tid >> 5;
    const int lane = tid & 31;
    const int mBase = blockIdx.x * 128;
    const int wm = (wid >> 1) * 32;
    const int wn = (wid & 1) * 32;
    const int K = g.K;

    if (tid < 64) sb_bias[tid] = g.bias[tid];
    if (MODE == 2 && tid == 0) {
        float s0 = g_s[g.sIdx]   * (1.f/(float)NTn);
        float s1 = g_s[g.sIdx+1] * (1.f/(float)NTn);
        float mm = fmaxf(s0, s1);
        float e0 = expf(s0 - mm), e1 = expf(s1 - mm);
        sb_beta[0] = e0 / (e0 + e1);
        sb_beta[1] = e1 / (e0 + e1);
    }
    __syncthreads();
    float cb0 = 0.f, cb1 = 0.f;
    if (MODE == 2) { cb0 = sb_beta[0]; cb1 = sb_beta[1]; }

    float d[2][4][4];
    #pragma unroll
    for (int mt = 0; mt < 2; mt++)
        #pragma unroll
        for (int nt = 0; nt < 4; nt++)
            #pragma unroll
            for (int f = 0; f < 4; f++) d[mt][nt][f] = 0.f;

    float4 ra0[8];
    uint4  r0b[4], r0s[4], r1b[4], r1s[4];
    uint4  rbb[2], rbs[2];
    int aRow[8], aCol[8];
    int mRow[4], mCol[4];
    int bRow[2], bCol[2];
    #pragma unroll
    for (int i = 0; i < 8; i++) {
        int t = tid + i*256;
        aRow[i] = t >> 4;
        aCol[i] = (t & 15) * 4;
    }
    #pragma unroll
    for (int i = 0; i < 4; i++) {
        int t = tid + i*256;
        mRow[i] = t >> 3;
        mCol[i] = (t & 7) * 8;
    }
    #pragma unroll
    for (int i = 0; i < 2; i++) {
        int t = tid + i*256;
        bRow[i] = t >> 3;
        bCol[i] = (t & 7) * 8;
    }

    auto loadRegs = [&](int c) {
        if (MODE == 0) {
            #pragma unroll
            for (int i = 0; i < 8; i++) {
                int gr = mBase + aRow[i];
                ra0[i] = (gr < M)
                    ? *(const float4*)(g.A0 + (size_t)gr*K + c*64 + aCol[i])
                    : make_float4(0.f,0.f,0.f,0.f);
            }
        } else {
            #pragma unroll
            for (int i = 0; i < 4; i++) {
                size_t off = (size_t)(mBase + mRow[i])*K + c*64 + mCol[i];
                r0b[i] = *(const uint4*)(g.A0b + off);
                r0s[i] = *(const uint4*)(g.A0s + off);
                r1b[i] = *(const uint4*)(g.A1b + off);
                r1s[i] = *(const uint4*)(g.A1s + off);
            }
        }
        #pragma unroll
        for (int i = 0; i < 2; i++) {
            rbb[i] = *(const uint4*)(g.Bb  + (size_t)bRow[i]*K + c*64 + bCol[i]);
            rbs[i] = *(const uint4*)(g.Bs2 + (size_t)bRow[i]*K + c*64 + bCol[i]);
        }
    };
    auto storeSmem = [&]() {
        if (MODE == 0) {
            #pragma unroll
            for (int i = 0; i < 8; i++) {
                float4 v = ra0[i];
                __nv_bfloat16 bx = __float2bfloat16_rn(v.x);
                __nv_bfloat16 by = __float2bfloat16_rn(v.y);
                __nv_bfloat16 bz = __float2bfloat16_rn(v.z);
                __nv_bfloat16 bw = __float2bfloat16_rn(v.w);
                uint2 ub, us;
                ub.x = pk2(bx, by);  ub.y = pk2(bz, bw);
                us.x = pk2(__float2bfloat16_rn(v.x - bf2f(bx)),
                           __float2bfloat16_rn(v.y - bf2f(by)));
                us.y = pk2(__float2bfloat16_rn(v.z - bf2f(bz)),
                           __float2bfloat16_rn(v.w - bf2f(bw)));
                *(uint2*)&AsB[aRow[i]*AP + aCol[i]] = ub;
                *(uint2*)&AsS[aRow[i]*AP + aCol[i]] = us;
            }
        } else {
            #pragma unroll
            for (int i = 0; i < 4; i++) {
                const __nv_bfloat16* p0b = (const __nv_bfloat16*)&r0b[i];
                const __nv_bfloat16* p0s = (const __nv_bfloat16*)&r0s[i];
                const __nv_bfloat16* p1b = (const __nv_bfloat16*)&r1b[i];
                const __nv_bfloat16* p1s = (const __nv_bfloat16*)&r1s[i];
                __nv_bfloat16 big[8], sml[8];
                #pragma unroll
                for (int k = 0; k < 8; k++) {
                    float v = cb0*(bf2f(p0b[k]) + bf2f(p0s[k]))
                            + cb1*(bf2f(p1b[k]) + bf2f(p1s[k]));
                    big[k] = __float2bfloat16_rn(v);
                    sml[k] = __float2bfloat16_rn(v - bf2f(big[k]));
                }
                uint4 ub, us;
                ub.x = pk2(big[0],big[1]); ub.y = pk2(big[2],big[3]);
                ub.z = pk2(big[4],big[5]); ub.w = pk2(big[6],big[7]);
                us.x = pk2(sml[0],sml[1]); us.y = pk2(sml[2],sml[3]);
                us.z = pk2(sml[4],sml[5]); us.w = pk2(sml[6],sml[7]);
                *(uint4*)&AsB[mRow[i]*AP + mCol[i]] = ub;
                *(uint4*)&AsS[mRow[i]*AP + mCol[i]] = us;
            }
        }
        #pragma unroll
        for (int i = 0; i < 2; i++) {
            *(uint4*)&BsB[bRow[i]*AP + bCol[i]] = rbb[i];
            *(uint4*)&BsS[bRow[i]*AP + bCol[i]] = rbs[i];
        }
    };

    uint32_t aBb = smem_u32(AsB), aSb = smem_u32(AsS);
    uint32_t bBb = smem_u32(BsB), bSb = smem_u32(BsS);

    const int chunks = K >> 6;
    loadRegs(0);
    #pragma unroll 1
    for (int c = 0; c < chunks; c++) {
        storeSmem();
        __syncthreads();
        if (c + 1 < chunks) loadRegs(c + 1);
        #pragma unroll
        for (int ks = 0; ks < 4; ks++) {
            uint32_t afB[2][4], afS[2][4];
            #pragma unroll
            for (int mt = 0; mt < 2; mt++) {
                uint32_t off = ((wm + mt*16 + (lane & 15))*AP + ks*16 + (lane >> 4)*8) << 1;
                asm volatile("ldmatrix.sync.aligned.m8n8.x4.shared.b16 {%0,%1,%2,%3}, [%4];"
                    : "=r"(afB[mt][0]), "=r"(afB[mt][1]), "=r"(afB[mt][2]), "=r"(afB[mt][3])
                    : "r"(aBb + off));
                asm volatile("ldmatrix.sync.aligned.m8n8.x4.shared.b16 {%0,%1,%2,%3}, [%4];"
                    : "=r"(afS[mt][0]), "=r"(afS[mt][1]), "=r"(afS[mt][2]), "=r"(afS[mt][3])
                    : "r"(aSb + off));
            }
            uint32_t bfB[4][2], bfS[4][2];
            #pragma unroll
            for (int ntp = 0; ntp < 2; ntp++) {
                uint32_t off = ((wn + ntp*16 + (lane & 15))*AP + ks*16 + (lane >> 4)*8) << 1;
                uint32_t r0, r1, r2, r3;
                asm volatile("ldmatrix.sync.aligned.m8n8.x4.shared.b16 {%0,%1,%2,%3}, [%4];"
                    : "=r"(r0), "=r"(r1), "=r"(r2), "=r"(r3) : "r"(bBb + off));
                bfB[ntp*2+0][0] = r0; bfB[ntp*2+0][1] = r2;
                bfB[ntp*2+1][0] = r1; bfB[ntp*2+1][1] = r3;
                asm volatile("ldmatrix.sync.aligned.m8n8.x4.shared.b16 {%0,%1,%2,%3}, [%4];"
                    : "=r"(r0), "=r"(r1), "=r"(r2), "=r"(r3) : "r"(bSb + off));
                bfS[ntp*2+0][0] = r0; bfS[ntp*2+0][1] = r2;
                bfS[ntp*2+1][0] = r1; bfS[ntp*2+1][1] = r3;
            }
            #pragma unroll
            for (int mt = 0; mt < 2; mt++)
                #pragma unroll
                for (int nt = 0; nt < 4; nt++) {
                    asm volatile(
                        "mma.sync.aligned.m16n8k16.row.col.f32.bf16.bf16.f32 "
                        "{%0,%1,%2,%3}, {%4,%5,%6,%7}, {%8,%9}, {%0,%1,%2,%3};"
                        : "+f"(d[mt][nt][0]), "+f"(d[mt][nt][1]),
                          "+f"(d[mt][nt][2]), "+f"(d[mt][nt][3])
                        : "r"(afB[mt][0]), "r"(afB[mt][1]), "r"(afB[mt][2]), "r"(afB[mt][3]),
                          "r"(bfB[nt][0]), "r"(bfB[nt][1]));
                    asm volatile(
                        "mma.sync.aligned.m16n8k16.row.col.f32.bf16.bf16.f32 "
                        "{%0,%1,%2,%3}, {%4,%5,%6,%7}, {%8,%9}, {%0,%1,%2,%3};"
                        : "+f"(d[mt][nt][0]), "+f"(d[mt][nt][1]),
                          "+f"(d[mt][nt][2]), "+f"(d[mt][nt][3])
                        : "r"(afB[mt][0]), "r"(afB[mt][1]), "r"(afB[mt][2]), "r"(afB[mt][3]),
                          "r"(bfS[nt][0]), "r"(bfS[nt][1]));
                    asm volatile(
                        "mma.sync.aligned.m16n8k16.row.col.f32.bf16.bf16.f32 "
                        "{%0,%1,%2,%3}, {%4,%5,%6,%7}, {%8,%9}, {%0,%1,%2,%3};"
                        : "+f"(d[mt][nt][0]), "+f"(d[mt][nt][1]),
                          "+f"(d[mt][nt][2]), "+f"(d[mt][nt][3])
                        : "r"(afS[mt][0]), "r"(afS[mt][1]), "r"(afS[mt][2]), "r"(afS[mt][3]),
                          "r"(bfB[nt][0]), "r"(bfB[nt][1]));
                }
        }
        __syncthreads();
    }

    int g8  = lane >> 2;
    int tig = lane & 3;
    #pragma unroll
    for (int mt = 0; mt < 2; mt++) {
        int r0 = mBase + wm + mt*16 + g8;
        int r1 = r0 + 8;
        #pragma unroll
        for (int nt = 0; nt < 4; nt++) {
            int c0 = wn + nt*8 + 2*tig;
            float x0 = d[mt][nt][0] + sb_bias[c0];
            float x1 = d[mt][nt][1] + sb_bias[c0+1];
            float x2 = d[mt][nt][2] + sb_bias[c0];
            float x3 = d[mt][nt][3] + sb_bias[c0+1];
            if (MODE == 2) {
                x0 = (x0 > 0.f) ? x0 : (__expf(x0) - 1.f);
                x1 = (x1 > 0.f) ? x1 : (__expf(x1) - 1.f);
                x2 = (x2 > 0.f) ? x2 : (__expf(x2) - 1.f);
                x3 = (x3 > 0.f) ? x3 : (__expf(x3) - 1.f);
            }
            if (r0 < M) {
                *(float2*)&g.C[(size_t)r0*DD + c0] = make_float2(x0, x1);
                *(uint32_t*)&g.Ch[(size_t)r0*DD + c0] =
                    pk2h(__float2half_rn(x0), __float2half_rn(x1));
            }
            if (r1 < M) {
                *(float2*)&g.C[(size_t)r1*DD + c0] = make_float2(x2, x3);
                *(uint32_t*)&g.Ch[(size_t)r1*DD + c0] =
                    pk2h(__float2half_rn(x2), __float2half_rn(x3));
            }
        }
    }
}

// ---------------- final logits at target rows (beta inline, split st) --------
__global__ __launch_bounds__(256)
void final_kernel(const __nv_bfloat16* __restrict__ stb0, const __nv_bfloat16* __restrict__ sts0,
                  const __nv_bfloat16* __restrict__ stb1, const __nv_bfloat16* __restrict__ sts1,
                  const float* __restrict__ lW1, const float* __restrict__ lb1,
                  const int* __restrict__ tgt, float* __restrict__ out) {
    int t    = blockIdx.x;
    int col  = threadIdx.x >> 5;
    int lane = threadIdx.x & 31;
    int n = tgt[t];
    float s0 = g_s[0] * (1.f/(float)NTn);
    float s1 = g_s[1] * (1.f/(float)NTn);
    float mm = fmaxf(s0, s1);
    float e0 = expf(s0 - mm), e1 = expf(s1 - mm);
    float b0 = e0 / (e0 + e1), b1 = e1 / (e0 + e1);
    float acc = 0.f;
    for (int k = lane; k < HDIM; k += 32) {
        size_t idx = (size_t)n*HDIM + k;
        float a = b0*(bf2f(stb0[idx]) + bf2f(sts0[idx]))
                + b1*(bf2f(stb1[idx]) + bf2f(sts1[idx]));
        acc += a * lW1[(size_t)k*COUT + col];
    }
    #pragma unroll
    for (int o = 16; o > 0; o >>= 1) acc += __shfl_xor_sync(0xffffffffu, acc, o);
    if (lane == 0) out[(size_t)t*COUT + col] = acc + lb1[col];
}

// ---------------- host orchestration ----------------
extern "C" void kernel_launch(void* const* d_in, const int* in_sizes, int n_in,
                              void* d_out, int out_size) {
    const float* X0   = (const float*)d_in[0];
    const float* X1   = (const float*)d_in[1];
    const float* X2   = (const float*)d_in[2];
    const float* fcW[3] = {(const float*)d_in[3], (const float*)d_in[5], (const float*)d_in[7]};
    const float* fcb[3] = {(const float*)d_in[4], (const float*)d_in[6], (const float*)d_in[8]};
    const float* attn1 = (const float*)d_in[9];
    const float* attn2 = (const float*)d_in[10];
    const float* mpW   = (const float*)d_in[11];
    const float* mpb   = (const float*)d_in[12];
    const float* mpq   = (const float*)d_in[13];
    const float* lW0   = (const float*)d_in[14];
    const float* lb0   = (const float*)d_in[15];
    const float* lW1   = (const float*)d_in[16];
    const float* lb1   = (const float*)d_in[17];
    const int*   mpidx = (const int*)d_in[18];
    const int*   tgt   = (const int*)d_in[19];
    float* out = (float*)d_out;

    float *h0, *h1, *sp;
    __half *hhp;
    __nv_bfloat16 *stbp, *stsp, *btp, *wbp, *wsp;
    int *cnt, *ofs, *cur;
    cudaGetSymbolAddress((void**)&h0,   g_h0);
    cudaGetSymbolAddress((void**)&h1,   g_h1);
    cudaGetSymbolAddress((void**)&hhp,  g_hh);
    cudaGetSymbolAddress((void**)&stbp, g_stb);
    cudaGetSymbolAddress((void**)&stsp, g_sts);
    cudaGetSymbolAddress((void**)&sp,   g_s);
    cudaGetSymbolAddress((void**)&cnt,  g_counts);
    cudaGetSymbolAddress((void**)&ofs,  g_ofs);
    cudaGetSymbolAddress((void**)&cur,  g_cursor);
    cudaGetSymbolAddress((void**)&btp,  g_bt);
    cudaGetSymbolAddress((void**)&wbp,  g_wb);
    cudaGetSymbolAddress((void**)&wsp,  g_ws);

    const size_t SLABST = (size_t)NTn*HDIM;
    const int mTiles = (NTn + 127) / 128;

    // 1-3: CSR build (counts zero-init at load; scan re-zeroes each run)
    hist_kernel   <<<dim3((ECNT+255)/256, 1, NSLAB), 256>>>(mpidx, cnt);
    scan_kernel   <<<NSLAB, 1024>>>(cnt, ofs, cur);
    scatter_kernel<<<dim3((ECNT+255)/256, 1, NSLAB), 256>>>(mpidx, cur);

    // 4: weight prep (fc/lW0 split + mpW transpose)
    {
        PArgs4 pa = {};
        pa.z[0] = {fcW[0], 512, WOFF0};
        pa.z[1] = {fcW[1], 256, WOFF1};
        pa.z[2] = {fcW[2], 128, WOFF2};
        pa.z[3] = {lW0,    512, WOFF3};
        prepW_kernel<<<dim3((AVd*HDIM + 255)/256, 1, 8), 256>>>(pa, mpW);
    }

    // 5: feature FC -> h0 (+ fp16 mirror)
    {
        HArgsN ga = {};
        const float* Xs[3] = {X0, X1, X2};
        const int    Ks[3] = {512, 256, 128};
        const int    Wo[3] = {WOFF0, WOFF1, WOFF2};
        for (int i = 0; i < NTYPES; i++) {
            ga.z[i].A0 = Xs[i];
            ga.z[i].Bb = wbp + Wo[i]; ga.z[i].Bs2 = wsp + Wo[i];
            ga.z[i].bias = fcb[i];
            ga.z[i].C  = h0  + (size_t)i*NTn*DD;
            ga.z[i].Ch = hhp + (size_t)i*NTn*DD;
            ga.z[i].K = Ks[i];
        }
        hgemm_kernel<0><<<dim3(mTiles, 1, NTYPES), 256>>>(NTn, ga);
    }

    for (int l = 0; l < 2; l++) {
        const float* hin = (l == 0) ? h0 : h1;
        int nslab  = (l == 0) ? NSLAB : NMP;
        int ntypes = (l == 0) ? NTYPES : 1;

        dot_kernel <<<dim3((NNODES+7)/8, 1, ntypes), 256>>>(hin, attn1, attn2, l*NSLAB);
        node_kernel<<<dim3((NTn+7)/8, 1, nslab), 256>>>(hhp, hin);

        {
            T1ArgsN ga = {};
            for (int zz = 0; zz < nslab; zz++) {
                int type = (l == 0) ? (zz / NMP) : 0;
                int mi = (l == 0) ? type : NTYPES;
                int bi = l*NTYPES + type;
                ga.z[zz].A    = stbp + (size_t)zz*SLABST;
                ga.z[zz].Bt   = btp + (size_t)mi*AVd*HDIM;
                ga.z[zz].bias = mpb + (size_t)bi*AVd;
                ga.z[zz].q    = mpq + (size_t)bi*AVd;
                ga.z[zz].sOut = sp + zz;
            }
            mp_attn_kernel<<<dim3(mTiles, 1, nslab), 256>>>(NTn, ga);
        }

        if (l == 0) {
            HArgsN ga = {};
            for (int t = 0; t < NTYPES; t++) {
                ga.z[t].A0b = stbp + (size_t)(t*2+0)*SLABST;
                ga.z[t].A0s = stsp + (size_t)(t*2+0)*SLABST;
                ga.z[t].A1b = stbp + (size_t)(t*2+1)*SLABST;
                ga.z[t].A1s = stsp + (size_t)(t*2+1)*SLABST;
                ga.z[t].Bb = wbp + WOFF3; ga.z[t].Bs2 = wsp + WOFF3;
                ga.z[t].bias = lb0;
                ga.z[t].C  = h1  + (size_t)t*NTn*DD;
                ga.z[t].Ch = hhp + (size_t)t*NTn*DD;
                ga.z[t].K = HDIM;
                ga.z[t].sIdx = t*2;
            }
            hgemm_kernel<2><<<dim3(mTiles, 1, NTYPES), 256>>>(NTn, ga);
        } else {
            final_kernel<<<NTGTn, 256>>>(stbp, stsp, stbp + SLABST, stsp + SLABST,
                                         lW1, lb1, tgt, out);
        }
    }
}

// round 13
// speedup vs baseline: 1.0940x; 1.0940x over previous
#include <cuda_runtime.h>
#include <cuda_bf16.h>
#include <cuda_fp16.h>
#include <math.h>
#include <stdint.h>

#define NTn     34000
#define NTYPES  3
#define NMP     2
#define ECNT    300000
#define HH      8
#define DD      64
#define HDIM    512
#define AVd     128
#define COUT    8
#define NTGTn   1000
#define NNODES  (NTYPES*NTn)
#define NSLAB   (NTYPES*NMP)

// ---------------- scratch (device globals; no allocation) ----------------
__device__ float g_h0[(size_t)NNODES*DD];
__device__ float g_h1[(size_t)NNODES*DD];
__device__ __half g_hh[(size_t)NNODES*DD];   // fp16 mirror of current-layer h (gathers)
// st as single fp16; +128 rows padding so tile tails stay in-bounds (zero-init)
__device__ __half g_sth[((size_t)NSLAB*NTn + 128)*HDIM];
__device__ float g_u [(size_t)NSLAB*NTn*HH];
__device__ float g_t2[(size_t)NSLAB*NNODES*HH];
__device__ int2  g_srt[(size_t)NSLAB*ECNT];      // sorted (n1,n2); n0 = ibase + segment
__device__ int   g_counts[NSLAB*NTn];            // zero-init at load; scan re-zeroes
__device__ int   g_ofs   [NSLAB*NTn];
__device__ int   g_cursor[NSLAB*NTn];
__device__ float g_s[NSLAB];
__device__ __half g_bt[(size_t)(NTYPES+1)*AVd*HDIM];  // mpW^T fp16 (4 matrices)
__device__ __half g_wh[64*512];                        // lW0^T fp16 [64][512]
// split-bf16 transposed fc weights [64][K]: fc0(K512), fc1(K256), fc2(K128)
#define WOFF0 0
#define WOFF1 (64*512)
#define WOFF2 (WOFF1 + 64*256)
#define WTOT  (WOFF2 + 64*128)
__device__ __nv_bfloat16 g_wb[WTOT];
__device__ __nv_bfloat16 g_ws[WTOT];

__device__ __forceinline__ float tanh_apx(float x) {
    float y; asm("tanh.approx.f32 %0, %1;" : "=f"(y) : "f"(x)); return y;
}
__device__ __forceinline__ uint32_t smem_u32(const void* p) {
    uint32_t a;
    asm("{ .reg .u64 t; cvta.to.shared.u64 t, %1; cvt.u32.u64 %0, t; }"
        : "=r"(a) : "l"(p));
    return a;
}
__device__ __forceinline__ float bf2f(__nv_bfloat16 x) { return __bfloat162float(x); }
__device__ __forceinline__ uint32_t pk2(__nv_bfloat16 a, __nv_bfloat16 b) {
    __nv_bfloat162 p = __halves2bfloat162(a, b);
    return *(uint32_t*)&p;
}
__device__ __forceinline__ uint32_t pk2h(__half a, __half b) {
    __half2 p = __halves2half2(a, b);
    return *(uint32_t*)&p;
}

// ---------------- weight prep: fc split-transpose + lW0/mpW fp16 transpose ----
struct PArgs { const float* W; int K; int off; };
struct PArgs3 { PArgs z[3]; };
__global__ void prepW_kernel(PArgs3 pa, const float* __restrict__ mpW,
                             const float* __restrict__ lW0) {
    int zz = blockIdx.z;
    int idx = blockIdx.x*256 + threadIdx.x;
    if (zz < 3) {               // fc weights: split-bf16 transpose
        PArgs g = pa.z[zz];
        if (idx < 64*g.K) {
            int n = idx & 63;
            int k = idx >> 6;
            float v = g.W[(size_t)k*64 + n];
            __nv_bfloat16 big = __float2bfloat16_rn(v);
            g_wb[g.off + (size_t)n*g.K + k] = big;
            g_ws[g.off + (size_t)n*g.K + k] = __float2bfloat16_rn(v - bf2f(big));
        }
    } else if (zz == 3) {       // lW0: fp16 transpose [64][512]
        if (idx < 64*512) {
            int n = idx & 63;
            int k = idx >> 6;
            g_wh[(size_t)n*512 + k] = __float2half_rn(lW0[(size_t)k*64 + n]);
        }
    } else {                    // mpW: fp16 transpose [AVd][HDIM]
        int mi = zz - 4;
        if (idx < AVd*HDIM) {
            int n = idx >> 9;
            int k = idx & 511;
            float v = mpW[(size_t)mi*HDIM*AVd + (size_t)k*AVd + n];
            g_bt[(size_t)mi*AVd*HDIM + (size_t)n*HDIM + k] = __float2half_rn(v);
        }
    }
}

// ---------------- CSR construction ----------------
__global__ void hist_kernel(const int* __restrict__ mpidx, int* __restrict__ counts) {
    int slab = blockIdx.z;
    int e = blockIdx.x*blockDim.x + threadIdx.x;
    if (e < ECNT) {
        int dst = mpidx[(size_t)slab*ECNT*3 + e*3] - (slab/NMP)*NTn;
        atomicAdd(&counts[(size_t)slab*NTn + dst], 1);
    }
}

__global__ void scan_kernel(int* __restrict__ countsAll,
                            int* __restrict__ ofsAll, int* __restrict__ cursorAll) {
    int slab = blockIdx.x;
    int4* counts4 = (int4*)(countsAll + (size_t)slab*NTn);
    int4* ofs4    = (int4*)(ofsAll    + (size_t)slab*NTn);
    int4* cursor4 = (int4*)(cursorAll + (size_t)slab*NTn);
    const int N4 = NTn/4;
    __shared__ int warp_sums[32];
    __shared__ int s_carry;
    if (threadIdx.x == 0) s_carry = 0;
    __syncthreads();
    int lane = threadIdx.x & 31, wid = threadIdx.x >> 5;
    for (int base = 0; base < N4; base += 1024) {
        int i4 = base + threadIdx.x;
        int4 v = (i4 < N4) ? counts4[i4] : make_int4(0,0,0,0);
        if (i4 < N4) counts4[i4] = make_int4(0,0,0,0);   // re-zero for next run
        int c1 = v.x, c2 = c1 + v.y, c3 = c2 + v.z, c4 = c3 + v.w;
        int tot = c4;
        int incl = tot;
        #pragma unroll
        for (int d = 1; d < 32; d <<= 1) {
            int t = __shfl_up_sync(0xffffffffu, incl, d);
            if (lane >= d) incl += t;
        }
        if (lane == 31) warp_sums[wid] = incl;
        __syncthreads();
        if (wid == 0) {
            int w = warp_sums[lane];
            #pragma unroll
            for (int d = 1; d < 32; d <<= 1) {
                int t = __shfl_up_sync(0xffffffffu, w, d);
                if (lane >= d) w += t;
            }
            warp_sums[lane] = w;
        }
        __syncthreads();
        int add = s_carry + (wid > 0 ? warp_sums[wid-1] : 0);
        int be  = add + incl - tot;
        if (i4 < N4) {
            int4 o = make_int4(be, be + c1, be + c2, be + c3);
            ofs4[i4] = o;
            cursor4[i4] = o;
        }
        __syncthreads();
        if (threadIdx.x == 1023) s_carry = add + incl;
        __syncthreads();
    }
}

__global__ void scatter_kernel(const int* __restrict__ mpidx, int* __restrict__ cursorAll) {
    int slab = blockIdx.z;
    int e = blockIdx.x*blockDim.x + threadIdx.x;
    if (e < ECNT) {
        const int* mp = mpidx + (size_t)slab*ECNT*3 + (size_t)e*3;
        int n0 = mp[0], n1 = mp[1], n2 = mp[2];
        int dst = n0 - (slab/NMP)*NTn;
        int pos = atomicAdd(&cursorAll[(size_t)slab*NTn + dst], 1);
        g_srt[(size_t)slab*ECNT + pos] = make_int2(n1, n2);
    }
}

// ---------------- per-node attention dots (warp/node, both metapaths of a type) ----
__global__ __launch_bounds__(256)
void dot_kernel(const float* __restrict__ h, const float* __restrict__ attn1,
                const float* __restrict__ attn2, int layerOff) {
    int type = blockIdx.z;
    size_t base = (size_t)(layerOff + type*NMP)*HH*DD;
    __shared__ float a1s[NMP*HH*DD];
    __shared__ float a2s[NMP*HH*DD];
    for (int i = threadIdx.x; i < NMP*HH*DD; i += blockDim.x) {
        a1s[i] = attn1[base + i];
        a2s[i] = attn2[base + i];
    }
    if (blockIdx.x == 0 && blockIdx.z == 0 && threadIdx.x < NSLAB)
        g_s[threadIdx.x] = 0.f;
    __syncthreads();
    int lane = threadIdx.x & 31;
    int wid  = threadIdx.x >> 5;
    int gn = blockIdx.x*8 + wid;
    if (gn >= NNODES) return;

    float hv0 = h[(size_t)gn*DD + lane];
    float hv1 = h[(size_t)gn*DD + 32 + lane];
    int ibase = type*NTn;
    bool isdst = (gn >= ibase) && (gn < ibase + NTn);
    const float third = 1.f/3.f;

    #pragma unroll
    for (int p = 0; p < NMP; p++) {
        int slab = type*NMP + p;
        const float* a2p = a2s + p*HH*DD;
        const float* a1p = a1s + p*HH*DD;
        float r2[HH], r1[HH];
        #pragma unroll
        for (int hh = 0; hh < HH; hh++) {
            float v = hv0*a2p[hh*DD+lane] + hv1*a2p[hh*DD+32+lane];
            #pragma unroll
            for (int o = 16; o > 0; o >>= 1) v += __shfl_xor_sync(0xffffffffu, v, o);
            r2[hh] = v;
        }
        if (isdst) {
            #pragma unroll
            for (int hh = 0; hh < HH; hh++) {
                float v = hv0*a1p[hh*DD+lane] + hv1*a1p[hh*DD+32+lane];
                #pragma unroll
                for (int o = 16; o > 0; o >>= 1) v += __shfl_xor_sync(0xffffffffu, v, o);
                r1[hh] = v;
            }
        }
        float myt2 = 0.f, myu = 0.f;
        #pragma unroll
        for (int hh = 0; hh < HH; hh++) {
            if (lane == hh) {
                myt2 = r2[hh];
                if (isdst) myu = r1[hh] + r2[hh]*third;
            }
        }
        if (lane < HH) {
            g_t2[((size_t)slab*NNODES + gn)*HH + lane] = myt2;
            if (isdst) g_u[((size_t)slab*NTn + (gn - ibase))*HH + lane] = myu;
        }
    }
}

// ---------------- fused logits + segment softmax + weighted sum (warp/node) -----
// fp16 mid-node gathers; n0 term fp32; single fp16 st output.
__global__ __launch_bounds__(256)
void node_kernel(const __half* __restrict__ hh16, const float* __restrict__ hf) {
    int slab = blockIdx.z;
    const int*  ofs = g_ofs + (size_t)slab*NTn;
    const int2* srt = g_srt + (size_t)slab*ECNT;
    const float* t2b = g_t2 + (size_t)slab*NNODES*HH;
    const float* ub  = g_u  + (size_t)slab*NTn*HH;
    __half* sth = g_sth + (size_t)slab*NTn*HDIM;

    int lane = threadIdx.x & 31;
    int wid  = threadIdx.x >> 5;
    int n = blockIdx.x*8 + wid;
    if (n >= NTn) return;

    int s0 = ofs[n];
    int s1 = (n < NTn-1) ? ofs[n+1] : ECNT;
    int d0 = 2*lane;
    if (s1 == s0) {   // empty segment -> st row = elu(0) = 0
        #pragma unroll
        for (int hd = 0; hd < HH; hd++)
            *(uint32_t*)&sth[(size_t)n*HDIM + hd*DD + d0] = 0u;
        return;
    }
    int ibase = (slab/NMP)*NTn;

    const int h_my = lane & 7;
    const int c_my = lane >> 3;
    float u_my = ub[(size_t)n*HH + h_my];
    float2 hn0p = *(const float2*)&hf[(size_t)(ibase+n)*DD + d0];
    float hn0a = hn0p.x;
    float hn0b = hn0p.y;
    const float third = 1.f/3.f;

    float den_l = 0.f;
    float acc[2*HH];
    #pragma unroll
    for (int k = 0; k < 2*HH; k++) acc[k] = 0.f;

    int2 cur[4];
    #pragma unroll
    for (int c = 0; c < 4; c++) {
        int jj = s0 + c; if (jj >= s1) jj = s1 - 1;
        cur[c] = srt[jj];
    }

    for (int j = s0; j < s1; j += 4) {
        int2 nxt[4];
        int jn = j + 4;
        #pragma unroll
        for (int c = 0; c < 4; c++) {
            int jj = jn + c; if (jj >= s1) jj = s1 - 1;
            nxt[c] = srt[jj];
        }
        int m = s1 - j; if (m > 4) m = 4;
        int nn1[4], nn2[4];
        #pragma unroll
        for (int c = 0; c < 4; c++) { nn1[c] = cur[c].x; nn2[c] = cur[c].y; }
        float ta = t2b[(size_t)nn1[c_my]*HH + h_my];
        float tb = t2b[(size_t)nn2[c_my]*HH + h_my];
        __half2 p1[4], p2[4];
        #pragma unroll
        for (int c = 0; c < 4; c++) {
            p1[c] = *(const __half2*)&hh16[(size_t)nn1[c]*DD + d0];
            p2[c] = *(const __half2*)&hh16[(size_t)nn2[c]*DD + d0];
        }
        float ev = u_my + (ta + tb)*third;
        ev = (ev > 0.f) ? ev : 0.2f*ev;
        float ex = (c_my < m) ? __expf(ev) : 0.f;
        den_l += ex;
        #pragma unroll
        for (int c = 0; c < 4; c++) {
            float2 f1 = __half22float2(p1[c]);
            float2 f2 = __half22float2(p2[c]);
            float sa = f1.x + f2.x;
            float sb = f1.y + f2.y;
            #pragma unroll
            for (int hd = 0; hd < HH; hd++) {
                float exh = __shfl_sync(0xffffffffu, ex, c*8 + hd);
                acc[hd*2+0] += exh * sa;
                acc[hd*2+1] += exh * sb;
            }
        }
        #pragma unroll
        for (int c = 0; c < 4; c++) cur[c] = nxt[c];
    }

    den_l += __shfl_xor_sync(0xffffffffu, den_l, 8);
    den_l += __shfl_xor_sync(0xffffffffu, den_l, 16);

    #pragma unroll
    for (int hd = 0; hd < HH; hd++) {
        float dh = __shfl_sync(0xffffffffu, den_l, hd);
        float inv = 1.f / dh;
        float v0 = (hn0a + acc[hd*2+0]*inv) * third;
        float v1 = (hn0b + acc[hd*2+1]*inv) * third;
        v0 = (v0 > 0.f) ? v0 : (__expf(v0) - 1.f);
        v1 = (v1 > 0.f) ? v1 : (__expf(v1) - 1.f);
        *(uint32_t*)&sth[(size_t)n*HDIM + hd*DD + d0] =
            pk2h(__float2half_rn(v0), __float2half_rn(v1));
    }
}

// ---------------- HMMA fp16 mode-1 GEMM: s += sum_rows(tanh(A@B^T + bias).q) ----
struct T1Args { const __half* A; const __half* Bt;
                const float* bias; const float* q; float* sOut; };
struct T1ArgsN { T1Args z[NSLAB]; };

__global__ __launch_bounds__(256)
void mp_attn_kernel(int M, T1ArgsN ga) {
    constexpr int AP = 72;
    __shared__ __align__(16) __half As[128*AP];
    __shared__ __align__(16) __half Bs[128*AP];
    __shared__ float sb_bias[128], sb_q[128];
    __shared__ float red[256];
    const T1Args g = ga.z[blockIdx.z];
    const int tid  = threadIdx.x;
    const int wid  = tid >> 5;
    const int lane = tid & 31;
    const int mBase = blockIdx.x * 128;
    const int wm = (wid >> 2) * 64;
    const int wn = (wid & 3) * 32;

    if (tid < 128) { sb_bias[tid] = g.bias[tid]; sb_q[tid] = g.q[tid]; }

    float d[4][4][4];
    #pragma unroll
    for (int mt = 0; mt < 4; mt++)
        #pragma unroll
        for (int nt = 0; nt < 4; nt++)
            #pragma unroll
            for (int f = 0; f < 4; f++) d[mt][nt][f] = 0.f;

    uint4 ra[4], rb[4];
    int rowm[4], colm[4];
    #pragma unroll
    for (int i = 0; i < 4; i++) {
        int t = tid + i*256;
        rowm[i] = t >> 3;
        colm[i] = (t & 7) * 8;
    }

    auto loadRegs = [&](int c) {
        #pragma unroll
        for (int i = 0; i < 4; i++) {
            ra[i] = *(const uint4*)(g.A  + (size_t)(mBase + rowm[i])*HDIM + c*64 + colm[i]);
            rb[i] = *(const uint4*)(g.Bt + (size_t)rowm[i]*HDIM + c*64 + colm[i]);
        }
    };
    auto storeSmem = [&]() {
        #pragma unroll
        for (int i = 0; i < 4; i++) {
            *(uint4*)&As[rowm[i]*AP + colm[i]] = ra[i];
            *(uint4*)&Bs[rowm[i]*AP + colm[i]] = rb[i];
        }
    };

    uint32_t aSb = smem_u32(As);
    uint32_t bSb = smem_u32(Bs);

    loadRegs(0);
    #pragma unroll 1
    for (int c = 0; c < 8; c++) {
        storeSmem();
        __syncthreads();
        if (c < 7) loadRegs(c + 1);
        #pragma unroll
        for (int ks = 0; ks < 4; ks++) {
            uint32_t af[4][4];
            #pragma unroll
            for (int mt = 0; mt < 4; mt++) {
                uint32_t addr = aSb +
                    (((wm + mt*16 + (lane & 15))*AP + ks*16 + (lane >> 4)*8) << 1);
                asm volatile("ldmatrix.sync.aligned.m8n8.x4.shared.b16 {%0,%1,%2,%3}, [%4];"
                    : "=r"(af[mt][0]), "=r"(af[mt][1]), "=r"(af[mt][2]), "=r"(af[mt][3])
                    : "r"(addr));
            }
            uint32_t bf[4][2];
            #pragma unroll
            for (int nt = 0; nt < 4; nt++) {
                uint32_t addr = bSb +
                    (((wn + nt*8 + (lane & 7))*AP + ks*16 + ((lane >> 3) & 1)*8) << 1);
                asm volatile("ldmatrix.sync.aligned.m8n8.x2.shared.b16 {%0,%1}, [%2];"
                    : "=r"(bf[nt][0]), "=r"(bf[nt][1])
                    : "r"(addr));
            }
            #pragma unroll
            for (int mt = 0; mt < 4; mt++)
                #pragma unroll
                for (int nt = 0; nt < 4; nt++)
                    asm volatile(
                        "mma.sync.aligned.m16n8k16.row.col.f32.f16.f16.f32 "
                        "{%0,%1,%2,%3}, {%4,%5,%6,%7}, {%8,%9}, {%0,%1,%2,%3};"
                        : "+f"(d[mt][nt][0]), "+f"(d[mt][nt][1]),
                          "+f"(d[mt][nt][2]), "+f"(d[mt][nt][3])
                        : "r"(af[mt][0]), "r"(af[mt][1]), "r"(af[mt][2]), "r"(af[mt][3]),
                          "r"(bf[nt][0]), "r"(bf[nt][1]));
        }
        __syncthreads();
    }

    int g8  = lane >> 2;
    int tig = lane & 3;
    float local = 0.f;
    #pragma unroll
    for (int mt = 0; mt < 4; mt++) {
        int r0 = mBase + wm + mt*16 + g8;
        int r1 = r0 + 8;
        #pragma unroll
        for (int nt = 0; nt < 4; nt++) {
            int c0 = wn + nt*8 + 2*tig;
            float b0v = sb_bias[c0],   q0v = sb_q[c0];
            float b1v = sb_bias[c0+1], q1v = sb_q[c0+1];
            if (r0 < M)
                local += tanh_apx(d[mt][nt][0] + b0v)*q0v
                       + tanh_apx(d[mt][nt][1] + b1v)*q1v;
            if (r1 < M)
                local += tanh_apx(d[mt][nt][2] + b0v)*q0v
                       + tanh_apx(d[mt][nt][3] + b1v)*q1v;
        }
    }
    red[tid] = local;
    __syncthreads();
    if (tid < 128) red[tid] += red[tid + 128];
    __syncthreads();
    if (tid < 64) red[tid] += red[tid + 64];
    __syncthreads();
    if (tid < 32) {
        float v = red[tid] + red[tid + 32];
        #pragma unroll
        for (int o = 16; o > 0; o >>= 1) v += __shfl_xor_sync(0xffffffffu, v, o);
        if (tid == 0) atomicAdd(g.sOut, v);
    }
}

// ---------------- split-bf16 HMMA feature FC: C = A0(fp32) @ W + bias ---------
struct HArgs { const float* A0;
               const __nv_bfloat16* Bb;  const __nv_bfloat16* Bs2;
               const float* bias; float* C; __half* Ch; int K; };
struct HArgsN { HArgs z[NTYPES]; };

__global__ __launch_bounds__(256)
void hgemm0_kernel(int M, HArgsN ga) {
    constexpr int AP = 72;
    __shared__ __align__(16) __nv_bfloat16 AsB[128*AP];
    __shared__ __align__(16) __nv_bfloat16 AsS[128*AP];
    __shared__ __align__(16) __nv_bfloat16 BsB[64*AP];
    __shared__ __align__(16) __nv_bfloat16 BsS[64*AP];
    __shared__ float sb_bias[64];
    const HArgs g = ga.z[blockIdx.z];
    const int tid  = threadIdx.x;
    const int wid  = tid >> 5;
    const int lane = tid & 31;
    const int mBase = blockIdx.x * 128;
    const int wm = (wid >> 1) * 32;
    const int wn = (wid & 1) * 32;
    const int K = g.K;

    if (tid < 64) sb_bias[tid] = g.bias[tid];
    __syncthreads();

    float d[2][4][4];
    #pragma unroll
    for (int mt = 0; mt < 2; mt++)
        #pragma unroll
        for (int nt = 0; nt < 4; nt++)
            #pragma unroll
            for (int f = 0; f < 4; f++) d[mt][nt][f] = 0.f;

    float4 ra0[8];
    uint4  rbb[2], rbs[2];
    int aRow[8], aCol[8];
    int bRow[2], bCol[2];
    #pragma unroll
    for (int i = 0; i < 8; i++) {
        int t = tid + i*256;
        aRow[i] = t >> 4;
        aCol[i] = (t & 15) * 4;
    }
    #pragma unroll
    for (int i = 0; i < 2; i++) {
        int t = tid + i*256;
        bRow[i] = t >> 3;
        bCol[i] = (t & 7) * 8;
    }

    auto loadRegs = [&](int c) {
        #pragma unroll
        for (int i = 0; i < 8; i++) {
            int gr = mBase + aRow[i];
            ra0[i] = (gr < M)
                ? *(const float4*)(g.A0 + (size_t)gr*K + c*64 + aCol[i])
                : make_float4(0.f,0.f,0.f,0.f);
        }
        #pragma unroll
        for (int i = 0; i < 2; i++) {
            rbb[i] = *(const uint4*)(g.Bb  + (size_t)bRow[i]*K + c*64 + bCol[i]);
            rbs[i] = *(const uint4*)(g.Bs2 + (size_t)bRow[i]*K + c*64 + bCol[i]);
        }
    };
    auto storeSmem = [&]() {
        #pragma unroll
        for (int i = 0; i < 8; i++) {
            float4 v = ra0[i];
            __nv_bfloat16 bx = __float2bfloat16_rn(v.x);
            __nv_bfloat16 by = __float2bfloat16_rn(v.y);
            __nv_bfloat16 bz = __float2bfloat16_rn(v.z);
            __nv_bfloat16 bw = __float2bfloat16_rn(v.w);
            uint2 ub, us;
            ub.x = pk2(bx, by);  ub.y = pk2(bz, bw);
            us.x = pk2(__float2bfloat16_rn(v.x - bf2f(bx)),
                       __float2bfloat16_rn(v.y - bf2f(by)));
            us.y = pk2(__float2bfloat16_rn(v.z - bf2f(bz)),
                       __float2bfloat16_rn(v.w - bf2f(bw)));
            *(uint2*)&AsB[aRow[i]*AP + aCol[i]] = ub;
            *(uint2*)&AsS[aRow[i]*AP + aCol[i]] = us;
        }
        #pragma unroll
        for (int i = 0; i < 2; i++) {
            *(uint4*)&BsB[bRow[i]*AP + bCol[i]] = rbb[i];
            *(uint4*)&BsS[bRow[i]*AP + bCol[i]] = rbs[i];
        }
    };

    uint32_t aBb = smem_u32(AsB), aSb = smem_u32(AsS);
    uint32_t bBb = smem_u32(BsB), bSb = smem_u32(BsS);

    const int chunks = K >> 6;
    loadRegs(0);
    #pragma unroll 1
    for (int c = 0; c < chunks; c++) {
        storeSmem();
        __syncthreads();
        if (c + 1 < chunks) loadRegs(c + 1);
        #pragma unroll
        for (int ks = 0; ks < 4; ks++) {
            uint32_t afB[2][4], afS[2][4];
            #pragma unroll
            for (int mt = 0; mt < 2; mt++) {
                uint32_t off = ((wm + mt*16 + (lane & 15))*AP + ks*16 + (lane >> 4)*8) << 1;
                asm volatile("ldmatrix.sync.aligned.m8n8.x4.shared.b16 {%0,%1,%2,%3}, [%4];"
                    : "=r"(afB[mt][0]), "=r"(afB[mt][1]), "=r"(afB[mt][2]), "=r"(afB[mt][3])
                    : "r"(aBb + off));
                asm volatile("ldmatrix.sync.aligned.m8n8.x4.shared.b16 {%0,%1,%2,%3}, [%4];"
                    : "=r"(afS[mt][0]), "=r"(afS[mt][1]), "=r"(afS[mt][2]), "=r"(afS[mt][3])
                    : "r"(aSb + off));
            }
            uint32_t bfB[4][2], bfS[4][2];
            #pragma unroll
            for (int ntp = 0; ntp < 2; ntp++) {
                uint32_t off = ((wn + ntp*16 + (lane & 15))*AP + ks*16 + (lane >> 4)*8) << 1;
                uint32_t r0, r1, r2, r3;
                asm volatile("ldmatrix.sync.aligned.m8n8.x4.shared.b16 {%0,%1,%2,%3}, [%4];"
                    : "=r"(r0), "=r"(r1), "=r"(r2), "=r"(r3) : "r"(bBb + off));
                bfB[ntp*2+0][0] = r0; bfB[ntp*2+0][1] = r2;
                bfB[ntp*2+1][0] = r1; bfB[ntp*2+1][1] = r3;
                asm volatile("ldmatrix.sync.aligned.m8n8.x4.shared.b16 {%0,%1,%2,%3}, [%4];"
                    : "=r"(r0), "=r"(r1), "=r"(r2), "=r"(r3) : "r"(bSb + off));
                bfS[ntp*2+0][0] = r0; bfS[ntp*2+0][1] = r2;
                bfS[ntp*2+1][0] = r1; bfS[ntp*2+1][1] = r3;
            }
            #pragma unroll
            for (int mt = 0; mt < 2; mt++)
                #pragma unroll
                for (int nt = 0; nt < 4; nt++) {
                    asm volatile(
                        "mma.sync.aligned.m16n8k16.row.col.f32.bf16.bf16.f32 "
                        "{%0,%1,%2,%3}, {%4,%5,%6,%7}, {%8,%9}, {%0,%1,%2,%3};"
                        : "+f"(d[mt][nt][0]), "+f"(d[mt][nt][1]),
                          "+f"(d[mt][nt][2]), "+f"(d[mt][nt][3])
                        : "r"(afB[mt][0]), "r"(afB[mt][1]), "r"(afB[mt][2]), "r"(afB[mt][3]),
                          "r"(bfB[nt][0]), "r"(bfB[nt][1]));
                    asm volatile(
                        "mma.sync.aligned.m16n8k16.row.col.f32.bf16.bf16.f32 "
                        "{%0,%1,%2,%3}, {%4,%5,%6,%7}, {%8,%9}, {%0,%1,%2,%3};"
                        : "+f"(d[mt][nt][0]), "+f"(d[mt][nt][1]),
                          "+f"(d[mt][nt][2]), "+f"(d[mt][nt][3])
                        : "r"(afB[mt][0]), "r"(afB[mt][1]), "r"(afB[mt][2]), "r"(afB[mt][3]),
                          "r"(bfS[nt][0]), "r"(bfS[nt][1]));
                    asm volatile(
                        "mma.sync.aligned.m16n8k16.row.col.f32.bf16.bf16.f32 "
                        "{%0,%1,%2,%3}, {%4,%5,%6,%7}, {%8,%9}, {%0,%1,%2,%3};"
                        : "+f"(d[mt][nt][0]), "+f"(d[mt][nt][1]),
                          "+f"(d[mt][nt][2]), "+f"(d[mt][nt][3])
                        : "r"(afS[mt][0]), "r"(afS[mt][1]), "r"(afS[mt][2]), "r"(afS[mt][3]),
                          "r"(bfB[nt][0]), "r"(bfB[nt][1]));
                }
        }
        __syncthreads();
    }

    int g8  = lane >> 2;
    int tig = lane & 3;
    #pragma unroll
    for (int mt = 0; mt < 2; mt++) {
        int r0 = mBase + wm + mt*16 + g8;
        int r1 = r0 + 8;
        #pragma unroll
        for (int nt = 0; nt < 4; nt++) {
            int c0 = wn + nt*8 + 2*tig;
            float x0 = d[mt][nt][0] + sb_bias[c0];
            float x1 = d[mt][nt][1] + sb_bias[c0+1];
            float x2 = d[mt][nt][2] + sb_bias[c0];
            float x3 = d[mt][nt][3] + sb_bias[c0+1];
            if (r0 < M) {
                *(float2*)&g.C[(size_t)r0*DD + c0] = make_float2(x0, x1);
                *(uint32_t*)&g.Ch[(size_t)r0*DD + c0] =
                    pk2h(__float2half_rn(x0), __float2half_rn(x1));
            }
            if (r1 < M) {
                *(float2*)&g.C[(size_t)r1*DD + c0] = make_float2(x2, x3);
                *(uint32_t*)&g.Ch[(size_t)r1*DD + c0] =
                    pk2h(__float2half_rn(x2), __float2half_rn(x3));
            }
        }
    }
}

// ---------------- fp16 HMMA layer FC: C = elu((b0*A0 + b1*A1) @ W + bias) -----
struct H2Args { const __half* A0; const __half* A1; const __half* W;
                const float* bias; float* C; __half* Ch; int sIdx; };
struct H2ArgsN { H2Args z[NTYPES]; };

__global__ __launch_bounds__(256)
void hgemm2_kernel(int M, H2ArgsN ga) {
    constexpr int AP = 72;
    __shared__ __align__(16) __half As[128*AP];
    __shared__ __align__(16) __half Ws[64*AP];
    __shared__ float sb_bias[64];
    __shared__ float sb_beta[2];
    const H2Args g = ga.z[blockIdx.z];
    const int tid  = threadIdx.x;
    const int wid  = tid >> 5;
    const int lane = tid & 31;
    const int mBase = blockIdx.x * 128;
    const int wm = (wid >> 1) * 32;
    const int wn = (wid & 1) * 32;

    if (tid < 64) sb_bias[tid] = g.bias[tid];
    if (tid == 0) {
        float s0 = g_s[g.sIdx]   * (1.f/(float)NTn);
        float s1 = g_s[g.sIdx+1] * (1.f/(float)NTn);
        float mm = fmaxf(s0, s1);
        float e0 = expf(s0 - mm), e1 = expf(s1 - mm);
        sb_beta[0] = e0 / (e0 + e1);
        sb_beta[1] = e1 / (e0 + e1);
    }
    __syncthreads();
    float cb0 = sb_beta[0], cb1 = sb_beta[1];

    float d[2][4][4];
    #pragma unroll
    for (int mt = 0; mt < 2; mt++)
        #pragma unroll
        for (int nt = 0; nt < 4; nt++)
            #pragma unroll
            for (int f = 0; f < 4; f++) d[mt][nt][f] = 0.f;

    uint4 r0h[4], r1h[4], rw[2];
    int mRow[4], mCol[4];
    int bRow[2], bCol[2];
    #pragma unroll
    for (int i = 0; i < 4; i++) {
        int t = tid + i*256;
        mRow[i] = t >> 3;          // 0..127
        mCol[i] = (t & 7) * 8;
    }
    #pragma unroll
    for (int i = 0; i < 2; i++) {
        int t = tid + i*256;
        bRow[i] = t >> 3;          // 0..63
        bCol[i] = (t & 7) * 8;
    }

    auto loadRegs = [&](int c) {
        #pragma unroll
        for (int i = 0; i < 4; i++) {
            size_t off = (size_t)(mBase + mRow[i])*HDIM + c*64 + mCol[i];
            r0h[i] = *(const uint4*)(g.A0 + off);
            r1h[i] = *(const uint4*)(g.A1 + off);
        }
        #pragma unroll
        for (int i = 0; i < 2; i++)
            rw[i] = *(const uint4*)(g.W + (size_t)bRow[i]*HDIM + c*64 + bCol[i]);
    };
    auto storeSmem = [&]() {
        #pragma unroll
        for (int i = 0; i < 4; i++) {
            const __half* p0 = (const __half*)&r0h[i];
            const __half* p1 = (const __half*)&r1h[i];
            __half ch[8];
            #pragma unroll
            for (int k = 0; k < 8; k++)
                ch[k] = __float2half_rn(cb0*__half2float(p0[k]) + cb1*__half2float(p1[k]));
            *(uint4*)&As[mRow[i]*AP + mCol[i]] = *(uint4*)ch;
        }
        #pragma unroll
        for (int i = 0; i < 2; i++)
            *(uint4*)&Ws[bRow[i]*AP + bCol[i]] = rw[i];
    };

    uint32_t aSb = smem_u32(As);
    uint32_t wSb = smem_u32(Ws);

    loadRegs(0);
    #pragma unroll 1
    for (int c = 0; c < 8; c++) {
        storeSmem();
        __syncthreads();
        if (c < 7) loadRegs(c + 1);
        #pragma unroll
        for (int ks = 0; ks < 4; ks++) {
            uint32_t af[2][4];
            #pragma unroll
            for (int mt = 0; mt < 2; mt++) {
                uint32_t off = ((wm + mt*16 + (lane & 15))*AP + ks*16 + (lane >> 4)*8) << 1;
                asm volatile("ldmatrix.sync.aligned.m8n8.x4.shared.b16 {%0,%1,%2,%3}, [%4];"
                    : "=r"(af[mt][0]), "=r"(af[mt][1]), "=r"(af[mt][2]), "=r"(af[mt][3])
                    : "r"(aSb + off));
            }
            uint32_t bf[4][2];
            #pragma unroll
            for (int ntp = 0; ntp < 2; ntp++) {
                uint32_t off = ((wn + ntp*16 + (lane & 15))*AP + ks*16 + (lane >> 4)*8) << 1;
                uint32_t r0, r1, r2, r3;
                asm volatile("ldmatrix.sync.aligned.m8n8.x4.shared.b16 {%0,%1,%2,%3}, [%4];"
                    : "=r"(r0), "=r"(r1), "=r"(r2), "=r"(r3) : "r"(wSb + off));
                bf[ntp*2+0][0] = r0; bf[ntp*2+0][1] = r2;
                bf[ntp*2+1][0] = r1; bf[ntp*2+1][1] = r3;
            }
            #pragma unroll
            for (int mt = 0; mt < 2; mt++)
                #pragma unroll
                for (int nt = 0; nt < 4; nt++)
                    asm volatile(
                        "mma.sync.aligned.m16n8k16.row.col.f32.f16.f16.f32 "
                        "{%0,%1,%2,%3}, {%4,%5,%6,%7}, {%8,%9}, {%0,%1,%2,%3};"
                        : "+f"(d[mt][nt][0]), "+f"(d[mt][nt][1]),
                          "+f"(d[mt][nt][2]), "+f"(d[mt][nt][3])
                        : "r"(af[mt][0]), "r"(af[mt][1]), "r"(af[mt][2]), "r"(af[mt][3]),
                          "r"(bf[nt][0]), "r"(bf[nt][1]));
        }
        __syncthreads();
    }

    int g8  = lane >> 2;
    int tig = lane & 3;
    #pragma unroll
    for (int mt = 0; mt < 2; mt++) {
        int r0 = mBase + wm + mt*16 + g8;
        int r1 = r0 + 8;
        #pragma unroll
        for (int nt = 0; nt < 4; nt++) {
            int c0 = wn + nt*8 + 2*tig;
            float x0 = d[mt][nt][0] + sb_bias[c0];
            float x1 = d[mt][nt][1] + sb_bias[c0+1];
            float x2 = d[mt][nt][2] + sb_bias[c0];
            float x3 = d[mt][nt][3] + sb_bias[c0+1];
            x0 = (x0 > 0.f) ? x0 : (__expf(x0) - 1.f);
            x1 = (x1 > 0.f) ? x1 : (__expf(x1) - 1.f);
            x2 = (x2 > 0.f) ? x2 : (__expf(x2) - 1.f);
            x3 = (x3 > 0.f) ? x3 : (__expf(x3) - 1.f);
            if (r0 < M) {
                *(float2*)&g.C[(size_t)r0*DD + c0] = make_float2(x0, x1);
                *(uint32_t*)&g.Ch[(size_t)r0*DD + c0] =
                    pk2h(__float2half_rn(x0), __float2half_rn(x1));
            }
            if (r1 < M) {
                *(float2*)&g.C[(size_t)r1*DD + c0] = make_float2(x2, x3);
                *(uint32_t*)&g.Ch[(size_t)r1*DD + c0] =
                    pk2h(__float2half_rn(x2), __float2half_rn(x3));
            }
        }
    }
}

// ---------------- final logits at target rows (beta inline, fp16 st) --------
__global__ __launch_bounds__(256)
void final_kernel(const __half* __restrict__ st0, const __half* __restrict__ st1,
                  const float* __restrict__ lW1, const float* __restrict__ lb1,
                  const int* __restrict__ tgt, float* __restrict__ out) {
    int t    = blockIdx.x;
    int col  = threadIdx.x >> 5;
    int lane = threadIdx.x & 31;
    int n = tgt[t];
    float s0 = g_s[0] * (1.f/(float)NTn);
    float s1 = g_s[1] * (1.f/(float)NTn);
    float mm = fmaxf(s0, s1);
    float e0 = expf(s0 - mm), e1 = expf(s1 - mm);
    float b0 = e0 / (e0 + e1), b1 = e1 / (e0 + e1);
    float acc = 0.f;
    for (int k = lane; k < HDIM; k += 32) {
        size_t idx = (size_t)n*HDIM + k;
        float a = b0*__half2float(st0[idx]) + b1*__half2float(st1[idx]);
        acc += a * lW1[(size_t)k*COUT + col];
    }
    #pragma unroll
    for (int o = 16; o > 0; o >>= 1) acc += __shfl_xor_sync(0xffffffffu, acc, o);
    if (lane == 0) out[(size_t)t*COUT + col] = acc + lb1[col];
}

// ---------------- host orchestration ----------------
extern "C" void kernel_launch(void* const* d_in, const int* in_sizes, int n_in,
                              void* d_out, int out_size) {
    const float* X0   = (const float*)d_in[0];
    const float* X1   = (const float*)d_in[1];
    const float* X2   = (const float*)d_in[2];
    const float* fcW[3] = {(const float*)d_in[3], (const float*)d_in[5], (const float*)d_in[7]};
    const float* fcb[3] = {(const float*)d_in[4], (const float*)d_in[6], (const float*)d_in[8]};
    const float* attn1 = (const float*)d_in[9];
    const float* attn2 = (const float*)d_in[10];
    const float* mpW   = (const float*)d_in[11];
    const float* mpb   = (const float*)d_in[12];
    const float* mpq   = (const float*)d_in[13];
    const float* lW0   = (const float*)d_in[14];
    const float* lb0   = (const float*)d_in[15];
    const float* lW1   = (const float*)d_in[16];
    const float* lb1   = (const float*)d_in[17];
    const int*   mpidx = (const int*)d_in[18];
    const int*   tgt   = (const int*)d_in[19];
    float* out = (float*)d_out;

    float *h0, *h1, *sp;
    __half *hhp, *sthp, *btp, *whp;
    __nv_bfloat16 *wbp, *wsp;
    int *cnt, *ofs, *cur;
    cudaGetSymbolAddress((void**)&h0,   g_h0);
    cudaGetSymbolAddress((void**)&h1,   g_h1);
    cudaGetSymbolAddress((void**)&hhp,  g_hh);
    cudaGetSymbolAddress((void**)&sthp, g_sth);
    cudaGetSymbolAddress((void**)&sp,   g_s);
    cudaGetSymbolAddress((void**)&cnt,  g_counts);
    cudaGetSymbolAddress((void**)&ofs,  g_ofs);
    cudaGetSymbolAddress((void**)&cur,  g_cursor);
    cudaGetSymbolAddress((void**)&btp,  g_bt);
    cudaGetSymbolAddress((void**)&whp,  g_wh);
    cudaGetSymbolAddress((void**)&wbp,  g_wb);
    cudaGetSymbolAddress((void**)&wsp,  g_ws);

    const size_t SLABST = (size_t)NTn*HDIM;
    const int mTiles = (NTn + 127) / 128;

    // CSR build (counts zero-init at load; scan re-zeroes each run)
    hist_kernel   <<<dim3((ECNT+255)/256, 1, NSLAB), 256>>>(mpidx, cnt);
    scan_kernel   <<<NSLAB, 1024>>>(cnt, ofs, cur);
    scatter_kernel<<<dim3((ECNT+255)/256, 1, NSLAB), 256>>>(mpidx, cur);

    // weight prep (fc split + lW0/mpW fp16 transpose)
    {
        PArgs3 pa = {};
        pa.z[0] = {fcW[0], 512, WOFF0};
        pa.z[1] = {fcW[1], 256, WOFF1};
        pa.z[2] = {fcW[2], 128, WOFF2};
        prepW_kernel<<<dim3((AVd*HDIM + 255)/256, 1, 8), 256>>>(pa, mpW, lW0);
    }

    // feature FC -> h0 (+ fp16 mirror)
    {
        HArgsN ga = {};
        const float* Xs[3] = {X0, X1, X2};
        const int    Ks[3] = {512, 256, 128};
        const int    Wo[3] = {WOFF0, WOFF1, WOFF2};
        for (int i = 0; i < NTYPES; i++) {
            ga.z[i].A0 = Xs[i];
            ga.z[i].Bb = wbp + Wo[i]; ga.z[i].Bs2 = wsp + Wo[i];
            ga.z[i].bias = fcb[i];
            ga.z[i].C  = h0  + (size_t)i*NTn*DD;
            ga.z[i].Ch = hhp + (size_t)i*NTn*DD;
            ga.z[i].K = Ks[i];
        }
        hgemm0_kernel<<<dim3(mTiles, 1, NTYPES), 256>>>(NTn, ga);
    }

    for (int l = 0; l < 2; l++) {
        const float* hin = (l == 0) ? h0 : h1;
        int nslab  = (l == 0) ? NSLAB : NMP;
        int ntypes = (l == 0) ? NTYPES : 1;

        dot_kernel <<<dim3((NNODES+7)/8, 1, ntypes), 256>>>(hin, attn1, attn2, l*NSLAB);
        node_kernel<<<dim3((NTn+7)/8, 1, nslab), 256>>>(hhp, hin);

        {
            T1ArgsN ga = {};
            for (int zz = 0; zz < nslab; zz++) {
                int type = (l == 0) ? (zz / NMP) : 0;
                int mi = (l == 0) ? type : NTYPES;
                int bi = l*NTYPES + type;
                ga.z[zz].A    = sthp + (size_t)zz*SLABST;
                ga.z[zz].Bt   = btp + (size_t)mi*AVd*HDIM;
                ga.z[zz].bias = mpb + (size_t)bi*AVd;
                ga.z[zz].q    = mpq + (size_t)bi*AVd;
                ga.z[zz].sOut = sp + zz;
            }
            mp_attn_kernel<<<dim3(mTiles, 1, nslab), 256>>>(NTn, ga);
        }

        if (l == 0) {
            H2ArgsN ga = {};
            for (int t = 0; t < NTYPES; t++) {
                ga.z[t].A0 = sthp + (size_t)(t*2+0)*SLABST;
                ga.z[t].A1 = sthp + (size_t)(t*2+1)*SLABST;
                ga.z[t].W  = whp;
                ga.z[t].bias = lb0;
                ga.z[t].C  = h1  + (size_t)t*NTn*DD;
                ga.z[t].Ch = hhp + (size_t)t*NTn*DD;
                ga.z[t].sIdx = t*2;
            }
            hgemm2_kernel<<<dim3(mTiles, 1, NTYPES), 256>>>(NTn, ga);
        } else {
            final_kernel<<<NTGTn, 256>>>(sthp, sthp + SLABST, lW1, lb1, tgt, out);
        }
    }
}